// round 16
// baseline (speedup 1.0000x reference)
#include <cuda_runtime.h>
#include <cuda_bf16.h>
#include <cstdint>

// Problem shape (fixed)
#define BB_ 64
#define SS_ 512
#define HH_ 1024
#define LL_ 9

#define TPB 256
#define WARPS 8
#define ROWS_PER_BLOCK 32
#define NCHUNK 16               // 512/32 mask chunks

#define GSTRIDE 26              // u64 per 4-k group (208 B -> 52 words == 20 mod 32 banks)
#define KSLOT   6               // u64 per k within group (48 B)
#define NGROUP  (HH_ / 4)       // 256 groups

typedef unsigned long long u64;

// Bank-engineered packed W: group g holds k = 4g..4g+3; within group, k uses
// slots [ (k&3)*6 .. +5 ): jp0..3 = (W[k][2jp],W[k][2jp+1]), jp4 = (W[k][8],0).
__device__ u64 g_Wpack7[NGROUP * GSTRIDE];   // 53248 B

__device__ __forceinline__ u64 fma2(u64 a, u64 b, u64 c) {
    u64 d;
    asm("fma.rn.f32x2 %0, %1, %2, %3;" : "=l"(d) : "l"(a), "l"(b), "l"(c));
    return d;
}
__device__ __forceinline__ u64 add2(u64 a, u64 b) {
    u64 d;
    asm("add.rn.f32x2 %0, %1, %2;" : "=l"(d) : "l"(a), "l"(b));
    return d;
}
__device__ __forceinline__ u64 pack2(float lo, float hi) {
    u64 d;
    asm("mov.b64 %0, {%1, %2};" : "=l"(d) : "f"(lo), "f"(hi));
    return d;
}
__device__ __forceinline__ void unpack2(float& lo, float& hi, u64 v) {
    asm("mov.b64 {%0, %1}, %2;" : "=f"(lo), "=f"(hi) : "l"(v));
}

// ---------------------------------------------------------------------------
// One-shot: W [H,L] -> g_Wpack7 (grouped, bank-swizzled)
// ---------------------------------------------------------------------------
__global__ void pack_W7(const float* __restrict__ W) {
    int k = blockIdx.x * 256 + threadIdx.x;   // 0..1023
    u64* dst = g_Wpack7 + (size_t)(k >> 2) * GSTRIDE + (k & 3) * KSLOT;
    #pragma unroll
    for (int jp = 0; jp < 4; jp++)
        dst[jp] = pack2(W[k * LL_ + 2 * jp], W[k * LL_ + 2 * jp + 1]);
    dst[4] = pack2(W[k * LL_ + 8], 0.0f);
    dst[5] = 0ull;
}

// ---------------------------------------------------------------------------
// Per-k compute for one row: W broadcast-ish from bank-disjoint smem.
// ---------------------------------------------------------------------------
__device__ __forceinline__ void step1(float xs, const u64* wk, u64 acc[5]) {
    const ulonglong2* wp = (const ulonglong2*)wk;
    ulonglong2 w01 = wp[0];
    ulonglong2 w23 = wp[1];
    u64 w4 = wk[4];
    u64 xx = pack2(xs, xs);
    acc[0] = fma2(xx, w01.x, acc[0]);
    acc[1] = fma2(xx, w01.y, acc[1]);
    acc[2] = fma2(xx, w23.x, acc[2]);
    acc[3] = fma2(xx, w23.y, acc[3]);
    acc[4] = fma2(xx, w4,    acc[4]);
}

// ---------------------------------------------------------------------------
// Main kernel. Block = 32 rows of one batch. Warp w owns k-chunk [128w,128w+128).
// Lane quad (g = lane>>2 picks row, q = lane&3 picks 16B of the row's 64B slab)
// processes 8 rows per pass, 4 passes. Quad reduce = 2 shfl rounds.
// W smem layout gives conflict-free (1-phase) LDS for the 4 quad k's.
// ---------------------------------------------------------------------------
extern __shared__ u64 dynsm[];
// [0, 6656)          : sW7 (53248 B)
// [6656, 7936)       : part[warp(8)][row(32)][jp(5)] u64 (10240 B)

__global__ __launch_bounds__(TPB, 3)
void bertner_main_kernel(const float* __restrict__ seq,
                         const int* __restrict__ mask,
                         const float* __restrict__ bias,
                         float* __restrict__ out) {
    u64* sW7  = dynsm;
    u64* part = dynsm + NGROUP * GSTRIDE;

    __shared__ unsigned mbits[NCHUNK];
    __shared__ int msum[NCHUNK];
    __shared__ int ssrc[ROWS_PER_BLOCK];
    __shared__ int snv;
    __shared__ float sb[LL_];

    int tid  = threadIdx.x;
    int lane = tid & 31;
    int warp = tid >> 5;

    int b  = blockIdx.x >> 4;                 // 16 blocks per batch
    int d0 = (blockIdx.x & 15) * ROWS_PER_BLOCK;

    if (tid < LL_) sb[tid] = bias[tid];

    // ---- per-block mask scan (512 bits) ----
    #pragma unroll
    for (int r = 0; r < 2; r++) {
        int chunk = warp * 2 + r;
        int s = chunk * 32 + lane;
        int m = (mask[b * SS_ + s] != 0);
        unsigned bal = __ballot_sync(0xffffffffu, m);
        if (lane == 0) mbits[chunk] = bal;
    }
    __syncthreads();
    if (tid < NCHUNK) {
        int v = __popc(mbits[tid]);
        #pragma unroll
        for (int off = 1; off < NCHUNK; off <<= 1) {
            int u = __shfl_up_sync(0x0000ffffu, v, off);
            if (tid >= off) v += u;
        }
        msum[tid] = v;
        if (tid == NCHUNK - 1) snv = v;
    }
    __syncthreads();
    int nv = snv;

    if (d0 >= nv) {
        // whole block invalid: softmax(bias) for its 32 rows
        if (tid < ROWS_PER_BLOCK) {
            float l[LL_];
            float mx = -3.402823466e+38f;
            #pragma unroll
            for (int j = 0; j < LL_; j++) { l[j] = sb[j]; mx = fmaxf(mx, l[j]); }
            float ssum = 0.0f;
            #pragma unroll
            for (int j = 0; j < LL_; j++) { l[j] = __expf(l[j] - mx); ssum += l[j]; }
            float inv = __fdividef(1.0f, ssum);
            float* o = out + (size_t)(b * SS_ + d0 + tid) * LL_;
            #pragma unroll
            for (int j = 0; j < LL_; j++) o[j] = l[j] * inv;
        }
        return;
    }
    int nrow = nv - d0;
    if (nrow > ROWS_PER_BLOCK) nrow = ROWS_PER_BLOCK;

    // ---- source index for this block's 32 rows ----
    if (tid < ROWS_PER_BLOCK) {
        int d = d0 + tid;
        int src = 0;
        if (d < nv) {
            int c = 0, base = 0;
            #pragma unroll
            for (int cc = 0; cc < NCHUNK - 1; cc++)
                if (msum[cc] <= d) { c = cc + 1; base = msum[cc]; }
            unsigned wv = mbits[c];
            int rr = d - base;
            for (int t = 0; t < rr; t++) wv &= wv - 1;
            src = c * 32 + (__ffs(wv) - 1);
        }
        ssrc[tid] = src;
    }

    // ---- stage packed W into smem (53248 B, coalesced float4 copy) ----
    {
        const float4* g = (const float4*)g_Wpack7;
        float4* dd = (float4*)sW7;
        #pragma unroll
        for (int it = 0; it < (NGROUP * GSTRIDE * 8 / 16) / TPB; it++)   // 13
            dd[it * TPB + tid] = g[it * TPB + tid];
    }
    __syncthreads();

    // ---- main GEMV: 4 passes of 8 rows; quad per row ----
    int q = lane & 3;
    int g = lane >> 2;                        // 0..7
    float4 z4 = make_float4(0.f, 0.f, 0.f, 0.f);

    #pragma unroll
    for (int pass = 0; pass < 4; pass++) {
        int row = pass * 8 + g;
        u64 acc[5];
        #pragma unroll
        for (int jp = 0; jp < 5; jp++) acc[jp] = 0ull;

        if (pass * 8 < nrow) {                // warp-uniform
            bool vR = row < nrow;
            const float4* xp = (const float4*)seq +
                ((size_t)(b * SS_ + ssrc[row]) * 256) + warp * 32;
            float4 cx = z4;
            if (vR) cx = __ldg(xp + q);
            int gq0 = warp * 32 + q;          // base group index for this lane

            #pragma unroll
            for (int rr = 0; rr < 8; rr++) {
                float4 nx = z4;
                if (rr < 7 && vR) nx = __ldg(xp + (rr + 1) * 4 + q);
                const u64* wg = sW7 + (size_t)(gq0 + rr * 4) * GSTRIDE;
                step1(cx.x, wg + 0 * KSLOT, acc);
                step1(cx.y, wg + 1 * KSLOT, acc);
                step1(cx.z, wg + 2 * KSLOT, acc);
                step1(cx.w, wg + 3 * KSLOT, acc);
                cx = nx;
            }
            // quad reduce (k split across q=0..3 of the SAME row)
            #pragma unroll
            for (int jp = 0; jp < 5; jp++)
                acc[jp] = add2(acc[jp], __shfl_xor_sync(0xffffffffu, acc[jp], 1));
            #pragma unroll
            for (int jp = 0; jp < 5; jp++)
                acc[jp] = add2(acc[jp], __shfl_xor_sync(0xffffffffu, acc[jp], 2));
        }

        if (q == 0) {
            u64* pp = part + (size_t)warp * 160 + row * 5;
            #pragma unroll
            for (int jp = 0; jp < 5; jp++) pp[jp] = acc[jp];
        }
    }
    __syncthreads();

    // ---- combine the 8 k-chunks: 160 cells, 8-way sum each ----
    if (tid < 160) {
        u64 s = part[tid];
        #pragma unroll
        for (int w = 1; w < 8; w++) s = add2(s, part[w * 160 + tid]);
        part[tid] = s;
    }
    __syncthreads();

    // ---- epilogue: thread rr < 32 -> row rr ----
    if (tid < ROWS_PER_BLOCK) {
        float l[LL_ + 1];
        float lo, hi;
        unpack2(lo, hi, part[tid * 5 + 0]); l[0] = lo; l[1] = hi;
        unpack2(lo, hi, part[tid * 5 + 1]); l[2] = lo; l[3] = hi;
        unpack2(lo, hi, part[tid * 5 + 2]); l[4] = lo; l[5] = hi;
        unpack2(lo, hi, part[tid * 5 + 3]); l[6] = lo; l[7] = hi;
        unpack2(lo, hi, part[tid * 5 + 4]); l[8] = lo;
        float mx = -3.402823466e+38f;
        #pragma unroll
        for (int j = 0; j < LL_; j++) { l[j] += sb[j]; mx = fmaxf(mx, l[j]); }
        float ssum = 0.0f;
        #pragma unroll
        for (int j = 0; j < LL_; j++) { l[j] = __expf(l[j] - mx); ssum += l[j]; }
        float inv = __fdividef(1.0f, ssum);
        float* o = out + (size_t)(b * SS_ + d0 + tid) * LL_;
        #pragma unroll
        for (int j = 0; j < LL_; j++) o[j] = l[j] * inv;
    }
}

// ---------------------------------------------------------------------------
#define DYN_SMEM ((NGROUP * GSTRIDE + 8 * 32 * 5) * 8)   // 53248 + 10240 = 63488 B

extern "C" void kernel_launch(void* const* d_in, const int* in_sizes, int n_in,
                              void* d_out, int out_size) {
    const float* seq  = (const float*)d_in[0];   // [B,S,H] f32
    const int*   mask = (const int*)d_in[1];     // [B,S]   i32
    const float* W    = (const float*)d_in[2];   // [H,L]   f32
    const float* bias = (const float*)d_in[3];   // [L]     f32
    float* out = (float*)d_out;                  // [B,S,L] f32

    cudaFuncSetAttribute(bertner_main_kernel,
                         cudaFuncAttributeMaxDynamicSharedMemorySize, DYN_SMEM);

    pack_W7<<<HH_ / 256, 256>>>(W);

    int grid = (BB_ * SS_) / ROWS_PER_BLOCK;     // 1024
    bertner_main_kernel<<<grid, TPB, DYN_SMEM>>>(seq, mask, bias, out);
}